// round 14
// baseline (speedup 1.0000x reference)
#include <cuda_runtime.h>
#include <cuda_fp16.h>
#include <cstdint>

#define N_ROWS 32768
#define D_DIM  2048
#define B_DIM  2048

// ---------------- device scratch ----------------
__device__ float g_sumsq[N_ROWS];
__device__ float g_wa[N_ROWS];
__device__ float g_part[16 * D_DIM];
__device__ float g_colsum[D_DIM];
__device__ int   g_active[N_ROWS];
__device__ int   g_count;
__device__ int   g_maxbits;
__device__ int   g_qbucket;
__device__ float g_scale;
__device__ __half g_Wh[(size_t)N_ROWS * D_DIM];   // 64 MB
__device__ __half g_xh[(size_t)B_DIM * D_DIM];    // 8 MB

// ---------------- PTX helpers (baseline ISA only) ----------------
__device__ __forceinline__ uint32_t smem_u32(const void* p) {
    uint32_t a;
    asm("{ .reg .u64 t; cvta.to.shared.u64 t, %1; cvt.u32.u64 %0, t; }" : "=r"(a) : "l"(p));
    return a;
}
__device__ __forceinline__ void cpa16(uint32_t saddr, const void* g) {
    asm volatile("cp.async.cg.shared.global [%0], [%1], 16;" :: "r"(saddr), "l"(g));
}
#define CP_COMMIT() asm volatile("cp.async.commit_group;" ::: "memory")
#define CP_WAIT2()  asm volatile("cp.async.wait_group 2;" ::: "memory")

__device__ __forceinline__ void ldsm_x4(uint32_t* r, uint32_t addr) {
    asm volatile("ldmatrix.sync.aligned.m8n8.x4.shared.b16 {%0,%1,%2,%3}, [%4];"
        : "=r"(r[0]), "=r"(r[1]), "=r"(r[2]), "=r"(r[3]) : "r"(addr));
}
__device__ __forceinline__ void mma_f16(float* c, const uint32_t* a, const uint32_t* b) {
    asm volatile("mma.sync.aligned.m16n8k16.row.col.f32.f16.f16.f32 "
        "{%0,%1,%2,%3}, {%4,%5,%6,%7}, {%8,%9}, {%0,%1,%2,%3};"
        : "+f"(c[0]), "+f"(c[1]), "+f"(c[2]), "+f"(c[3])
        : "r"(a[0]), "r"(a[1]), "r"(a[2]), "r"(a[3]), "r"(b[0]), "r"(b[1]));
}

// ---------------- init ----------------
__global__ void k_init() { g_count = 0; g_maxbits = 0; }

// -------- per-row stats + W -> f16 --------
__global__ __launch_bounds__(256) void k_rowstats(const float* __restrict__ W,
                                                  const float* __restrict__ a) {
    int row = blockIdx.x;
    int tid = threadIdx.x;
    const float4* wr = reinterpret_cast<const float4*>(W + (size_t)row * D_DIM);
    const float4* a4 = reinterpret_cast<const float4*>(a);
    __half2* wh = reinterpret_cast<__half2*>(g_Wh + (size_t)row * D_DIM);

    float ss = 0.f, wa = 0.f;
#pragma unroll
    for (int i = 0; i < 2; i++) {
        int idx = tid + i * 256;            // 512 float4 per row
        float4 w  = wr[idx];
        float4 av = __ldg(&a4[idx]);
        ss += w.x * w.x + w.y * w.y + w.z * w.z + w.w * w.w;
        wa += w.x * av.x + w.y * av.y + w.z * av.z + w.w * av.w;
        wh[idx * 2 + 0] = __floats2half2_rn(w.x, w.y);
        wh[idx * 2 + 1] = __floats2half2_rn(w.z, w.w);
    }
    for (int o = 16; o; o >>= 1) {
        ss += __shfl_down_sync(0xFFFFFFFFu, ss, o);
        wa += __shfl_down_sync(0xFFFFFFFFu, wa, o);
    }
    __shared__ float sss[8], swa[8];
    int wid = tid >> 5, lane = tid & 31;
    if (lane == 0) { sss[wid] = ss; swa[wid] = wa; }
    __syncthreads();
    if (tid == 0) {
        double S = 0.0, A = 0.0;
#pragma unroll
        for (int i = 0; i < 8; i++) { S += sss[i]; A += swa[i]; }
        float Sf = (float)S;
        g_sumsq[row] = Sf;
        g_wa[row]    = (float)A;
        atomicMax(&g_maxbits, __float_as_int(Sf));
    }
}

// -------- x -> f16 --------
__global__ __launch_bounds__(256) void k_convx(const float* __restrict__ x) {
    int i = blockIdx.x * 256 + threadIdx.x;
    float4 v = reinterpret_cast<const float4*>(x)[i];
    __half2* xh = reinterpret_cast<__half2*>(g_xh);
    xh[i * 2 + 0] = __floats2half2_rn(v.x, v.y);
    xh[i * 2 + 1] = __floats2half2_rn(v.z, v.w);
}

// -------- column sums of x: stage 1 (deterministic partials) --------
__global__ __launch_bounds__(256) void k_colsum1(const float* __restrict__ x) {
    int d = blockIdx.x * 256 + threadIdx.x;
    int p = blockIdx.y;                       // 16 row-partitions of 128 rows
    const float* xp = x + (size_t)p * 128 * D_DIM + d;
    float s0 = 0.f, s1 = 0.f;
    for (int b = 0; b < 128; b += 2) {
        s0 += xp[(size_t)b * D_DIM];
        s1 += xp[(size_t)(b + 1) * D_DIM];
    }
    g_part[p * D_DIM + d] = s0 + s1;
}
// -------- stage 2: fixed-order combine --------
__global__ __launch_bounds__(256) void k_colsum2() {
    int d = blockIdx.x * 256 + threadIdx.x;
    double s = 0.0;
#pragma unroll
    for (int p = 0; p < 16; p++) s += (double)g_part[p * D_DIM + d];
    g_colsum[d] = (float)s;
}

// -------- q bucket + scale --------
__global__ __launch_bounds__(256) void k_qhash(const float* __restrict__ a) {
    __shared__ double s_n2[256], s_ca[256];
    int t = threadIdx.x;
    double n2 = 0.0, ca = 0.0;
    for (int d = t; d < D_DIM; d += 256) {
        float c = g_colsum[d];
        n2 += (double)c * (double)c;
        ca += (double)c * (double)a[d];
    }
    s_n2[t] = n2; s_ca[t] = ca;
    __syncthreads();
    for (int off = 128; off; off >>= 1) {
        if (t < off) { s_n2[t] += s_n2[t + off]; s_ca[t] += s_ca[t + off]; }
        __syncthreads();
    }
    if (t == 0) {
        float nrm = sqrtf((float)s_n2[0]);
        float qd  = (float)s_ca[0] / nrm;
        float tail = a[D_DIM] + a[D_DIM + 1] + a[D_DIM + 2] + a[D_DIM + 3] + a[D_DIM + 4];
        float acc = qd + 0.5f * tail;
        float h = floorf(acc * 0.25f);
        long long hi = (long long)h;
        int b = (int)(hi % 64); if (b < 0) b += 64;
        g_qbucket = b;
        g_scale = 0.83f / sqrtf(__int_as_float(g_maxbits));
    }
}

// -------- mask + deterministic sorted compaction --------
__global__ __launch_bounds__(1024) void k_scan(const float* __restrict__ a) {
    __shared__ int cnts[1024];
    int t = threadIdx.x;
    float s  = g_scale;
    float s2 = s * s;
    float a0 = a[D_DIM], a1 = a[D_DIM + 1], a2 = a[D_DIM + 2],
          a3 = a[D_DIM + 3], a4 = a[D_DIM + 4];
    int qb = g_qbucket;

    unsigned mask = 0u;
#pragma unroll 4
    for (int r = 0; r < 32; r++) {
        int i = (t << 5) | r;
        float n2  = s2 * g_sumsq[i];
        float acc = s * g_wa[i];
        float p = n2;              acc += p * a0;
        p *= p;                    acc += p * a1;
        p *= p;                    acc += p * a2;
        p *= p;                    acc += p * a3;
        p *= p;                    acc += p * a4;
        float h = floorf(acc * 0.25f);
        int b = (int)((long long)h % 64); if (b < 0) b += 64;
        if (b == qb) mask |= (1u << r);
    }
    int lc = __popc(mask);
    cnts[t] = lc;
    __syncthreads();
    for (int off = 1; off < 1024; off <<= 1) {
        int v = (t >= off) ? cnts[t - off] : 0;
        __syncthreads();
        cnts[t] += v;
        __syncthreads();
    }
    int off = cnts[t] - lc;
    for (int r = 0; r < 32; r++) {
        if ((mask >> r) & 1u) g_active[off++] = (t << 5) | r;
    }
    if (t == 1023) g_count = cnts[1023];
}

// ================= single-pass f16 mma.sync compacted GEMM =================
// R6 config (proven optimum): 128 threads (2x2 warps), CTA 128x128,
// warp 64x64, BK=64, NSTAGE=3, two syncs/chunk, wait_group 2, 2 CTAs/SM.
// NEW epilogue: contiguous column-span writes (values + zeros) -> no memset.
#define BM 128
#define BN 128
#define BK 64
#define NCHUNK (D_DIM / BK)
#define NSTAGE 3
#define ROWB   144                      // 64 f16 = 128B data + 16B pad
#define A_TILE_B (128 * ROWB)           // 18432 B
#define B_TILE_B (128 * ROWB)           // 18432 B
#define STAGE_B (A_TILE_B + B_TILE_B)   // 36864 B
#define GEMM_SMEM (1024 + NSTAGE * STAGE_B)   // 111616 B
#define VST 129                          // padded row stride (floats) for vals
#define SPAN 4096                        // map chunk (bytes)

__device__ __forceinline__ void load_stage(uint32_t sbase, const int* acts_s,
                                           int mrow0, int k0, int tid) {
#pragma unroll
    for (int i = 0; i < 8; i++) {
        int idx = tid + i * 128;                 // 1024 cpa16 for X tile (128 rows x 8)
        int r = idx >> 3, ch = idx & 7;
        size_t g = (size_t)(mrow0 + r) * D_DIM + k0 + ch * 8;
        cpa16(sbase + r * ROWB + ch * 16, g_xh + g);
    }
#pragma unroll
    for (int i = 0; i < 8; i++) {
        int idx = tid + i * 128;                 // 1024 cpa16 for W tile (128 rows x 8)
        int r = idx >> 3, ch = idx & 7;
        size_t g = (size_t)acts_s[r] * D_DIM + k0 + ch * 8;
        cpa16(sbase + A_TILE_B + r * ROWB + ch * 16, g_Wh + g);
    }
}

__global__ void __launch_bounds__(128, 2) k_gemm(float* __restrict__ out) {
    extern __shared__ char smem[];
    int cnt = g_count;
    int nt = blockIdx.y;
    int mt = blockIdx.x;
    int tid = threadIdx.x;
    int mrow0 = mt * BM;

    if (cnt == 0) {                      // degenerate: all-zero output
        if (nt == 0) {
            for (int r = 0; r < BM; r++) {
                float* orow = out + (size_t)(mrow0 + r) * N_ROWS;
                for (int i = tid; i < N_ROWS; i += 128) orow[i] = 0.f;
            }
        }
        return;
    }
    if (nt * BN >= cnt) return;

    int lane = tid & 31, w = tid >> 5;
    int wm = w & 1, wn = w >> 1;                 // 2 x 2 warps, warp tile 64x64
    uint32_t sb = smem_u32(smem);
    int* acts_s = (int*)smem;
    {
        int j = nt * BN + tid;
        acts_s[tid] = g_active[j < cnt ? j : cnt - 1];
    }
    __syncthreads();

    for (int s = 0; s < NSTAGE; s++) {
        load_stage(sb + 1024 + s * STAGE_B, acts_s, mrow0, s * BK, tid);
        CP_COMMIT();
    }

    float acc[4][8][4] = {};
    uint32_t a_ro = (uint32_t)(wm * 64 + (lane & 15)) * ROWB + (uint32_t)(lane >> 4) * 16;
    uint32_t b_ro = (uint32_t)(wn * 64 + ((lane >> 4) << 3) + (lane & 7)) * ROWB
                  + (uint32_t)((lane >> 3) & 1) * 16;

    int sidx = 0;
    for (int c = 0; c < NCHUNK; c++) {
        CP_WAIT2();
        __syncthreads();
        uint32_t st = sb + 1024 + sidx * STAGE_B;
#pragma unroll
        for (int ks = 0; ks < 4; ks++) {
            uint32_t ah[4][4], bq[4][4];
            uint32_t ab = st + a_ro + ks * 32;
            uint32_t bb = st + A_TILE_B + b_ro + ks * 32;
#pragma unroll
            for (int mi = 0; mi < 4; mi++)
                ldsm_x4(ah[mi], ab + mi * (16 * ROWB));
#pragma unroll
            for (int ng = 0; ng < 4; ng++)
                ldsm_x4(bq[ng], bb + ng * (16 * ROWB));
#pragma unroll
            for (int mi = 0; mi < 4; mi++)
#pragma unroll
                for (int ng = 0; ng < 4; ng++) {
                    mma_f16(acc[mi][2 * ng + 0], ah[mi], &bq[ng][0]);
                    mma_f16(acc[mi][2 * ng + 1], ah[mi], &bq[ng][2]);
                }
        }
        __syncthreads();
        int nc = c + NSTAGE;
        if (nc < NCHUNK)
            load_stage(sb + 1024 + sidx * STAGE_B, acts_s, mrow0, nc * BK, tid);
        CP_COMMIT();
        sidx = (sidx + 1 == NSTAGE) ? 0 : sidx + 1;
    }

    // ---- span epilogue: write contiguous original-column range (vals + 0s) ----
    __syncthreads();                             // all warps done with stage smem
    float* vals = (float*)(smem + 1024);         // [128][VST] floats (~66KB)
    uint8_t* map = (uint8_t*)(smem + 1024 + 128 * VST * 4);  // [SPAN]

#pragma unroll
    for (int mi = 0; mi < 4; mi++) {
        int r0 = wm * 64 + mi * 16 + (lane >> 2);
#pragma unroll
        for (int ni = 0; ni < 8; ni++) {
            int jl = wn * 64 + ni * 8 + (lane & 3) * 2;
            vals[r0 * VST + jl]           = acc[mi][ni][0];
            vals[r0 * VST + jl + 1]       = acc[mi][ni][1];
            vals[(r0 + 8) * VST + jl]     = acc[mi][ni][2];
            vals[(r0 + 8) * VST + jl + 1] = acc[mi][ni][3];
        }
    }
    int ta = (cnt + BN - 1) / BN;
    int lim = cnt - nt * BN; if (lim > BN) lim = BN;
    int cstart = (nt == 0) ? 0 : g_active[nt * BN - 1] + 1;
    int cend = (nt == ta - 1) ? N_ROWS : acts_s[BN - 1] + 1;
    __syncthreads();

    for (int c0 = cstart; c0 < cend; c0 += SPAN) {
        int Lc = cend - c0; if (Lc > SPAN) Lc = SPAN;
        for (int i = tid; i < Lc; i += 128) map[i] = 0xFF;
        __syncthreads();
        if (tid < lim) {
            int cx = acts_s[tid];
            if (cx >= c0 && cx < c0 + Lc) map[cx - c0] = (uint8_t)tid;
        }
        __syncthreads();
        for (int r = 0; r < BM; r++) {
            float* orow = out + (size_t)(mrow0 + r) * N_ROWS + c0;
            const float* vr = vals + r * VST;
            for (int i = tid; i < Lc; i += 128) {
                uint8_t m = map[i];
                orow[i] = (m != 0xFF) ? vr[m] : 0.f;
            }
        }
        __syncthreads();
    }
}

// ---------------- launch ----------------
extern "C" void kernel_launch(void* const* d_in, const int* in_sizes, int n_in,
                              void* d_out, int out_size) {
    const float* x = (const float*)d_in[0];   // [2048, 2048]
    const float* W = (const float*)d_in[1];   // [32768, 2048]
    const float* a = (const float*)d_in[2];   // [2053]
    float* out = (float*)d_out;               // [2048, 32768]

    cudaFuncSetAttribute(k_gemm, cudaFuncAttributeMaxDynamicSharedMemorySize, GEMM_SMEM);

    k_init<<<1, 1>>>();
    k_rowstats<<<N_ROWS, 256>>>(W, a);
    k_convx<<<(B_DIM * D_DIM / 4) / 256, 256>>>(x);
    dim3 csg(D_DIM / 256, 16);
    k_colsum1<<<csg, 256>>>(x);
    k_colsum2<<<D_DIM / 256, 256>>>();
    k_qhash<<<1, 256>>>(a);
    k_scan<<<1, 1024>>>(a);

    dim3 grid(B_DIM / BM, N_ROWS / BN);   // mt fast -> W tile L2 reuse
    k_gemm<<<grid, 128, GEMM_SMEM>>>(out);  // spans cover ALL columns -> no memset
}

// round 15
// speedup vs baseline: 1.1670x; 1.1670x over previous
#include <cuda_runtime.h>
#include <cuda_fp16.h>
#include <cstdint>

#define N_ROWS 32768
#define D_DIM  2048
#define B_DIM  2048

// ---------------- device scratch ----------------
__device__ float g_sumsq[N_ROWS];
__device__ float g_wa[N_ROWS];
__device__ float g_part[16 * D_DIM];
__device__ float g_colsum[D_DIM];
__device__ int   g_active[N_ROWS];
__device__ int   g_count;
__device__ int   g_maxbits;
__device__ int   g_qbucket;
__device__ float g_scale;
__device__ __half g_Wh[(size_t)N_ROWS * D_DIM];   // 64 MB
__device__ __half g_xh[(size_t)B_DIM * D_DIM];    // 8 MB

// ---------------- PTX helpers (baseline ISA only) ----------------
__device__ __forceinline__ uint32_t smem_u32(const void* p) {
    uint32_t a;
    asm("{ .reg .u64 t; cvta.to.shared.u64 t, %1; cvt.u32.u64 %0, t; }" : "=r"(a) : "l"(p));
    return a;
}
__device__ __forceinline__ void cpa16(uint32_t saddr, const void* g) {
    asm volatile("cp.async.cg.shared.global [%0], [%1], 16;" :: "r"(saddr), "l"(g));
}
#define CP_COMMIT() asm volatile("cp.async.commit_group;" ::: "memory")
#define CP_WAIT2()  asm volatile("cp.async.wait_group 2;" ::: "memory")

__device__ __forceinline__ void ldsm_x4(uint32_t* r, uint32_t addr) {
    asm volatile("ldmatrix.sync.aligned.m8n8.x4.shared.b16 {%0,%1,%2,%3}, [%4];"
        : "=r"(r[0]), "=r"(r[1]), "=r"(r[2]), "=r"(r[3]) : "r"(addr));
}
__device__ __forceinline__ void mma_f16(float* c, const uint32_t* a, const uint32_t* b) {
    asm volatile("mma.sync.aligned.m16n8k16.row.col.f32.f16.f16.f32 "
        "{%0,%1,%2,%3}, {%4,%5,%6,%7}, {%8,%9}, {%0,%1,%2,%3};"
        : "+f"(c[0]), "+f"(c[1]), "+f"(c[2]), "+f"(c[3])
        : "r"(a[0]), "r"(a[1]), "r"(a[2]), "r"(a[3]), "r"(b[0]), "r"(b[1]));
}

// -------- x -> f16 (block 0 also inits g_maxbits; launched FIRST) --------
__global__ __launch_bounds__(256) void k_convx(const float* __restrict__ x) {
    if (blockIdx.x == 0 && threadIdx.x == 0) g_maxbits = 0;
    int i = blockIdx.x * 256 + threadIdx.x;
    float4 v = reinterpret_cast<const float4*>(x)[i];
    __half2* xh = reinterpret_cast<__half2*>(g_xh);
    xh[i * 2 + 0] = __floats2half2_rn(v.x, v.y);
    xh[i * 2 + 1] = __floats2half2_rn(v.z, v.w);
}

// -------- per-row stats + W -> f16 --------
__global__ __launch_bounds__(256) void k_rowstats(const float* __restrict__ W,
                                                  const float* __restrict__ a) {
    int row = blockIdx.x;
    int tid = threadIdx.x;
    const float4* wr = reinterpret_cast<const float4*>(W + (size_t)row * D_DIM);
    const float4* a4 = reinterpret_cast<const float4*>(a);
    __half2* wh = reinterpret_cast<__half2*>(g_Wh + (size_t)row * D_DIM);

    float ss = 0.f, wa = 0.f;
#pragma unroll
    for (int i = 0; i < 2; i++) {
        int idx = tid + i * 256;            // 512 float4 per row
        float4 w  = wr[idx];
        float4 av = __ldg(&a4[idx]);
        ss += w.x * w.x + w.y * w.y + w.z * w.z + w.w * w.w;
        wa += w.x * av.x + w.y * av.y + w.z * av.z + w.w * av.w;
        wh[idx * 2 + 0] = __floats2half2_rn(w.x, w.y);
        wh[idx * 2 + 1] = __floats2half2_rn(w.z, w.w);
    }
    for (int o = 16; o; o >>= 1) {
        ss += __shfl_down_sync(0xFFFFFFFFu, ss, o);
        wa += __shfl_down_sync(0xFFFFFFFFu, wa, o);
    }
    __shared__ float sss[8], swa[8];
    int wid = tid >> 5, lane = tid & 31;
    if (lane == 0) { sss[wid] = ss; swa[wid] = wa; }
    __syncthreads();
    if (tid == 0) {
        double S = 0.0, A = 0.0;
#pragma unroll
        for (int i = 0; i < 8; i++) { S += sss[i]; A += swa[i]; }
        float Sf = (float)S;
        g_sumsq[row] = Sf;
        g_wa[row]    = (float)A;
        atomicMax(&g_maxbits, __float_as_int(Sf));
    }
}

// -------- column sums of x: stage 1 (deterministic partials) --------
__global__ __launch_bounds__(256) void k_colsum1(const float* __restrict__ x) {
    int d = blockIdx.x * 256 + threadIdx.x;
    int p = blockIdx.y;                       // 16 row-partitions of 128 rows
    const float* xp = x + (size_t)p * 128 * D_DIM + d;
    float s0 = 0.f, s1 = 0.f;
    for (int b = 0; b < 128; b += 2) {
        s0 += xp[(size_t)b * D_DIM];
        s1 += xp[(size_t)(b + 1) * D_DIM];
    }
    g_part[p * D_DIM + d] = s0 + s1;
}
// -------- stage 2: fixed-order combine --------
__global__ __launch_bounds__(256) void k_colsum2() {
    int d = blockIdx.x * 256 + threadIdx.x;
    double s = 0.0;
#pragma unroll
    for (int p = 0; p < 16; p++) s += (double)g_part[p * D_DIM + d];
    g_colsum[d] = (float)s;
}

// -------- q bucket + scale --------
__global__ __launch_bounds__(256) void k_qhash(const float* __restrict__ a) {
    __shared__ double s_n2[256], s_ca[256];
    int t = threadIdx.x;
    double n2 = 0.0, ca = 0.0;
    for (int d = t; d < D_DIM; d += 256) {
        float c = g_colsum[d];
        n2 += (double)c * (double)c;
        ca += (double)c * (double)a[d];
    }
    s_n2[t] = n2; s_ca[t] = ca;
    __syncthreads();
    for (int off = 128; off; off >>= 1) {
        if (t < off) { s_n2[t] += s_n2[t + off]; s_ca[t] += s_ca[t + off]; }
        __syncthreads();
    }
    if (t == 0) {
        float nrm = sqrtf((float)s_n2[0]);
        float qd  = (float)s_ca[0] / nrm;
        float tail = a[D_DIM] + a[D_DIM + 1] + a[D_DIM + 2] + a[D_DIM + 3] + a[D_DIM + 4];
        float acc = qd + 0.5f * tail;
        float h = floorf(acc * 0.25f);
        long long hi = (long long)h;
        int b = (int)(hi % 64); if (b < 0) b += 64;
        g_qbucket = b;
        g_scale = 0.83f / sqrtf(__int_as_float(g_maxbits));
    }
}

// -------- mask + deterministic sorted compaction --------
__global__ __launch_bounds__(1024) void k_scan(const float* __restrict__ a) {
    __shared__ int cnts[1024];
    int t = threadIdx.x;
    float s  = g_scale;
    float s2 = s * s;
    float a0 = a[D_DIM], a1 = a[D_DIM + 1], a2 = a[D_DIM + 2],
          a3 = a[D_DIM + 3], a4 = a[D_DIM + 4];
    int qb = g_qbucket;

    unsigned mask = 0u;
#pragma unroll 4
    for (int r = 0; r < 32; r++) {
        int i = (t << 5) | r;
        float n2  = s2 * g_sumsq[i];
        float acc = s * g_wa[i];
        float p = n2;              acc += p * a0;
        p *= p;                    acc += p * a1;
        p *= p;                    acc += p * a2;
        p *= p;                    acc += p * a3;
        p *= p;                    acc += p * a4;
        float h = floorf(acc * 0.25f);
        int b = (int)((long long)h % 64); if (b < 0) b += 64;
        if (b == qb) mask |= (1u << r);
    }
    int lc = __popc(mask);
    cnts[t] = lc;
    __syncthreads();
    for (int off = 1; off < 1024; off <<= 1) {
        int v = (t >= off) ? cnts[t - off] : 0;
        __syncthreads();
        cnts[t] += v;
        __syncthreads();
    }
    int off = cnts[t] - lc;
    for (int r = 0; r < 32; r++) {
        if ((mask >> r) & 1u) g_active[off++] = (t << 5) | r;
    }
    if (t == 1023) g_count = cnts[1023];
}

// ================= single-pass f16 mma.sync compacted GEMM =================
// R6 config (proven optimum): 128 threads (2x2 warps), CTA tile 128x128,
// warp tile 64x64, BK=64, NSTAGE=3, two syncs/chunk, wait_group 2, 2 CTAs/SM.
#define BM 128
#define BN 128
#define BK 64
#define NCHUNK (D_DIM / BK)
#define NSTAGE 3
#define ROWB   144                      // 64 f16 = 128B data + 16B pad
#define A_TILE_B (128 * ROWB)           // 18432 B
#define B_TILE_B (128 * ROWB)           // 18432 B
#define STAGE_B (A_TILE_B + B_TILE_B)   // 36864 B
#define GEMM_SMEM (1024 + NSTAGE * STAGE_B)

__device__ __forceinline__ void load_stage(uint32_t sbase, const int* acts_s,
                                           int mrow0, int k0, int tid) {
#pragma unroll
    for (int i = 0; i < 8; i++) {
        int idx = tid + i * 128;                 // 1024 cpa16 for X tile (128 rows x 8)
        int r = idx >> 3, ch = idx & 7;
        size_t g = (size_t)(mrow0 + r) * D_DIM + k0 + ch * 8;
        cpa16(sbase + r * ROWB + ch * 16, g_xh + g);
    }
#pragma unroll
    for (int i = 0; i < 8; i++) {
        int idx = tid + i * 128;                 // 1024 cpa16 for W tile (128 rows x 8)
        int r = idx >> 3, ch = idx & 7;
        size_t g = (size_t)acts_s[r] * D_DIM + k0 + ch * 8;
        cpa16(sbase + A_TILE_B + r * ROWB + ch * 16, g_Wh + g);
    }
}

__global__ void __launch_bounds__(128, 2) k_gemm(float* __restrict__ out) {
    extern __shared__ char smem[];
    int cnt = g_count;
    int nt = blockIdx.y;
    if (nt * BN >= cnt) return;
    int mt = blockIdx.x;
    int tid = threadIdx.x;
    int lane = tid & 31, w = tid >> 5;
    int wm = w & 1, wn = w >> 1;                 // 2 x 2 warps, warp tile 64x64
    uint32_t sb = smem_u32(smem);
    int* acts_s = (int*)smem;
    {
        int j = nt * BN + tid;
        acts_s[tid] = g_active[j < cnt ? j : cnt - 1];
    }
    __syncthreads();
    int mrow0 = mt * BM;

    for (int s = 0; s < NSTAGE; s++) {
        load_stage(sb + 1024 + s * STAGE_B, acts_s, mrow0, s * BK, tid);
        CP_COMMIT();
    }

    float acc[4][8][4] = {};
    uint32_t a_ro = (uint32_t)(wm * 64 + (lane & 15)) * ROWB + (uint32_t)(lane >> 4) * 16;
    uint32_t b_ro = (uint32_t)(wn * 64 + ((lane >> 4) << 3) + (lane & 7)) * ROWB
                  + (uint32_t)((lane >> 3) & 1) * 16;

    int sidx = 0;
    for (int c = 0; c < NCHUNK; c++) {
        CP_WAIT2();
        __syncthreads();
        uint32_t st = sb + 1024 + sidx * STAGE_B;
#pragma unroll
        for (int ks = 0; ks < 4; ks++) {
            uint32_t ah[4][4], bq[4][4];
            uint32_t ab = st + a_ro + ks * 32;
            uint32_t bb = st + A_TILE_B + b_ro + ks * 32;
#pragma unroll
            for (int mi = 0; mi < 4; mi++)
                ldsm_x4(ah[mi], ab + mi * (16 * ROWB));
#pragma unroll
            for (int ng = 0; ng < 4; ng++)
                ldsm_x4(bq[ng], bb + ng * (16 * ROWB));
#pragma unroll
            for (int mi = 0; mi < 4; mi++)
#pragma unroll
                for (int ng = 0; ng < 4; ng++) {
                    mma_f16(acc[mi][2 * ng + 0], ah[mi], &bq[ng][0]);
                    mma_f16(acc[mi][2 * ng + 1], ah[mi], &bq[ng][2]);
                }
        }
        __syncthreads();
        int nc = c + NSTAGE;
        if (nc < NCHUNK)
            load_stage(sb + 1024 + sidx * STAGE_B, acts_s, mrow0, nc * BK, tid);
        CP_COMMIT();
        sidx = (sidx + 1 == NSTAGE) ? 0 : sidx + 1;
    }

    // epilogue: scatter to out[row][acts[j]]
    int lim = cnt - nt * BN; if (lim > BN) lim = BN;
#pragma unroll
    for (int mi = 0; mi < 4; mi++) {
        int r0 = mrow0 + wm * 64 + mi * 16 + (lane >> 2);
        float* o0 = out + (size_t)r0 * N_ROWS;
        float* o1 = o0 + (size_t)8 * N_ROWS;
#pragma unroll
        for (int ni = 0; ni < 8; ni++) {
            int jl = wn * 64 + ni * 8 + (lane & 3) * 2;
            if (jl < lim) {
                int cx = acts_s[jl];
                o0[cx] = acc[mi][ni][0];
                o1[cx] = acc[mi][ni][2];
            }
            if (jl + 1 < lim) {
                int cx = acts_s[jl + 1];
                o0[cx] = acc[mi][ni][1];
                o1[cx] = acc[mi][ni][3];
            }
        }
    }
}

// ---------------- launch ----------------
extern "C" void kernel_launch(void* const* d_in, const int* in_sizes, int n_in,
                              void* d_out, int out_size) {
    const float* x = (const float*)d_in[0];   // [2048, 2048]
    const float* W = (const float*)d_in[1];   // [32768, 2048]
    const float* a = (const float*)d_in[2];   // [2053]
    float* out = (float*)d_out;               // [2048, 32768]

    cudaFuncSetAttribute(k_gemm, cudaFuncAttributeMaxDynamicSharedMemorySize, GEMM_SMEM);

    k_convx<<<(B_DIM * D_DIM / 4) / 256, 256>>>(x);   // block 0 inits g_maxbits
    k_rowstats<<<N_ROWS, 256>>>(W, a);
    dim3 csg(D_DIM / 256, 16);
    k_colsum1<<<csg, 256>>>(x);
    k_colsum2<<<D_DIM / 256, 256>>>();
    k_qhash<<<1, 256>>>(a);
    k_scan<<<1, 1024>>>(a);

    cudaMemsetAsync(d_out, 0, (size_t)out_size * sizeof(float));

    dim3 grid(B_DIM / BM, N_ROWS / BN);   // mt fast -> W tile L2 reuse
    k_gemm<<<grid, 128, GEMM_SMEM>>>(out);
}